// round 6
// baseline (speedup 1.0000x reference)
#include <cuda_runtime.h>
#include <math.h>

#define NB   128
#define NT   512
#define BR   32
#define STA  256      // unified activation row stride (no pad needed: broadcasts + contiguous stores)

// smem layout (floats)
#define OFF_A0    0
#define OFF_A1    (OFF_A0 + BR*STA)
#define OFF_A2    (OFF_A1 + BR*STA)
#define OFF_SW0   (OFF_A2 + BR*STA)
#define OFF_SW1   (OFF_SW0 + 32*256)
#define OFF_SWF   (OFF_SW1 + 32*256)
#define OFF_XS    (OFF_SWF + 256*32)          // 32 x 33
#define OFF_TE    (OFF_XS + 32*33)
#define OFF_HT    (OFF_TE + 16)
#define OFF_TF    (OFF_HT + 32)
#define OFF_CF    (OFF_TF + 16)
#define SMEM_FLOATS (OFF_CF + 16)
#define SMEM_BYTES  (SMEM_FLOATS * 4)

// ---- packed f32x2 helpers (2 exact fp32 FMAs / instruction) ----------------
#define FMA2(acc, aa, bb) \
    asm("fma.rn.f32x2 %0, %1, %2, %0;" : "+l"(acc) : "l"(aa), "l"(bb))
#define PACK_DUP(dst, fv) do { \
    unsigned _pi = __float_as_uint(fv); \
    asm("mov.b64 %0, {%1, %1};" : "=l"(dst) : "r"(_pi)); } while (0)
#define UNPACK2(lo, hi, src) do { \
    unsigned _u0, _u1; \
    asm("mov.b64 {%0, %1}, %2;" : "=r"(_u0), "=r"(_u1) : "l"(src)); \
    lo = __uint_as_float(_u0); hi = __uint_as_float(_u1); } while (0)

// ---------------- threefry2x32-20 (exact JAX) ------------------------------
__device__ __forceinline__ unsigned rotl32(unsigned x, int r) {
    return __funnelshift_l(x, x, r);
}
__device__ __forceinline__ void threefry2x32(unsigned k0, unsigned k1,
                                             unsigned &x0, unsigned &x1) {
    unsigned k2 = k0 ^ k1 ^ 0x1BD11BDAu;
#define TFR(r) { x0 += x1; x1 = rotl32(x1, r); x1 ^= x0; }
    x0 += k0; x1 += k1;
    TFR(13) TFR(15) TFR(26) TFR(6)
    x0 += k1; x1 += k2 + 1u;
    TFR(17) TFR(29) TFR(16) TFR(24)
    x0 += k2; x1 += k0 + 2u;
    TFR(13) TFR(15) TFR(26) TFR(6)
    x0 += k0; x1 += k1 + 3u;
    TFR(17) TFR(29) TFR(16) TFR(24)
    x0 += k1; x1 += k2 + 4u;
    TFR(13) TFR(15) TFR(26) TFR(6)
    x0 += k2; x1 += k0 + 5u;
#undef TFR
}

// ---------------- XLA ErfInv f32 (Giles) ------------------------------------
__device__ __forceinline__ float erfinv_xla(float x) {
    float w = -log1pf(-x * x);
    float p;
    if (w < 5.0f) {
        w -= 2.5f;
        p = 2.81022636e-08f;
        p = fmaf(p, w, 3.43273939e-07f);
        p = fmaf(p, w, -3.5233877e-06f);
        p = fmaf(p, w, -4.39150654e-06f);
        p = fmaf(p, w, 0.00021858087f);
        p = fmaf(p, w, -0.00125372503f);
        p = fmaf(p, w, -0.00417768164f);
        p = fmaf(p, w, 0.246640727f);
        p = fmaf(p, w, 1.50140941f);
    } else {
        w = sqrtf(w) - 3.0f;
        p = -0.000200214257f;
        p = fmaf(p, w, 0.000100950558f);
        p = fmaf(p, w, 0.00134934322f);
        p = fmaf(p, w, -0.00367342844f);
        p = fmaf(p, w, 0.00573950773f);
        p = fmaf(p, w, -0.0076224613f);
        p = fmaf(p, w, 0.00943887047f);
        p = fmaf(p, w, 1.00167406f);
        p = fmaf(p, w, 2.83297682f);
    }
    return p * x;
}

__device__ __forceinline__ float mish_f(float x) {
    if (x > 20.0f) return x;
    float u = expf(x);
    float s = u * (u + 2.0f);
    return x * (s / (s + 2.0f));
}

// ---------------- cp.async helpers ------------------------------------------
__device__ __forceinline__ void cp16(float* dst, const float* src) {
    unsigned sa = (unsigned)__cvta_generic_to_shared(dst);
    asm volatile("cp.async.cg.shared.global [%0], [%1], 16;\n" :: "r"(sa), "l"(src));
}
#define CP_COMMIT() asm volatile("cp.async.commit_group;\n" ::: "memory")
#define CP_WAIT(n)  asm volatile("cp.async.wait_group %0;\n" :: "n"(n) : "memory")

// stage one 32x256 weight chunk (rows >= `rows` zero-filled); NT=512 -> 4 iters
__device__ __forceinline__ void stage_chunk(float* SWb, const float* Wsrc,
                                            int rows, int tid) {
#pragma unroll
    for (int l = 0; l < 4; ++l) {
        int idx = l * NT + tid;        // 16B-chunk id
        int row = idx >> 6;
        if (row < rows) cp16(SWb + 4 * idx, Wsrc + 4 * idx);
        else *reinterpret_cast<float4*>(SWb + 4 * idx) = make_float4(0.f, 0.f, 0.f, 0.f);
    }
}

// ------------- dense (K -> 256), 32 rows, NT=512, 4x4 thread tiles ----------
template <int KP, int KREAL, bool DOMISH>
__device__ __forceinline__ void dense_layer(const float* __restrict__ W,
                                            const float* __restrict__ bias,
                                            const float* __restrict__ IN,
                                            float* __restrict__ OUT,
                                            float* __restrict__ SW0,
                                            float* __restrict__ SW1, int tid) {
    constexpr int NCH = KP / 32;
    const int ty = tid >> 6;          // 8 row-groups of 4 rows
    const int tx = tid & 63;          // 64 col-groups of 4 cols (2 packed pairs)
    unsigned long long acc0[4], acc1[4];
#pragma unroll
    for (int r = 0; r < 4; ++r) { acc0[r] = 0ull; acc1[r] = 0ull; }

    stage_chunk(SW0, W, (KREAL < 32 ? KREAL : 32), tid);
    CP_COMMIT();

    const float* inbase = IN + (ty * 4) * STA;

#pragma unroll 1
    for (int c = 0; c < NCH; ++c) {
        if (c + 1 < NCH) {
            int rows = KREAL - (c + 1) * 32;
            if (rows > 32) rows = 32;
            stage_chunk((c & 1) ? SW0 : SW1, W + (c + 1) * 32 * 256, rows, tid);
            CP_COMMIT();
            CP_WAIT(1);
        } else {
            CP_WAIT(0);
        }
        __syncthreads();
        const float* SW = (c & 1) ? SW1 : SW0;
        const float* inrow = inbase + c * 32;
#pragma unroll 2
        for (int k4 = 0; k4 < 32; k4 += 4) {
            float4 av[4];
#pragma unroll
            for (int r = 0; r < 4; ++r)
                av[r] = *reinterpret_cast<const float4*>(inrow + r * STA + k4);
#pragma unroll
            for (int kk = 0; kk < 4; ++kk) {
                const float* bp = SW + ((k4 + kk) << 8) + (tx << 2);
                unsigned long long b01 = *reinterpret_cast<const unsigned long long*>(bp);
                unsigned long long b23 = *reinterpret_cast<const unsigned long long*>(bp + 2);
#pragma unroll
                for (int r = 0; r < 4; ++r) {
                    float a = reinterpret_cast<const float*>(&av[r])[kk];
                    unsigned long long aa;
                    PACK_DUP(aa, a);
                    FMA2(acc0[r], aa, b01);
                    FMA2(acc1[r], aa, b23);
                }
            }
        }
        __syncthreads();
    }

    float4 bb = *reinterpret_cast<const float4*>(bias + (tx << 2));
#pragma unroll
    for (int r = 0; r < 4; ++r) {
        float v0, v1, v2, v3;
        UNPACK2(v0, v1, acc0[r]);
        UNPACK2(v2, v3, acc1[r]);
        v0 += bb.x; v1 += bb.y; v2 += bb.z; v3 += bb.w;
        if (DOMISH) { v0 = mish_f(v0); v1 = mish_f(v1); v2 = mish_f(v2); v3 = mish_f(v3); }
        *reinterpret_cast<float4*>(OUT + (ty * 4 + r) * STA + (tx << 2)) =
            make_float4(v0, v1, v2, v3);
    }
}

// ---------------- persistent sampler: all 1000 steps in one kernel ----------
__global__ void __launch_bounds__(NT, 1)
diff_all(const float* __restrict__ state, const float* __restrict__ x_init,
         const float* __restrict__ w_t1, const float* __restrict__ b_t1,
         const float* __restrict__ w_t2, const float* __restrict__ b_t2,
         const float* __restrict__ w0,  const float* __restrict__ b0,
         const float* __restrict__ w1,  const float* __restrict__ b1,
         const float* __restrict__ w2,  const float* __restrict__ b2,
         const float* __restrict__ wf,  const float* __restrict__ bf,
         float* __restrict__ outp)
{
    extern __shared__ float sm[];
    float*    A0   = sm + OFF_A0;
    float*    A1   = sm + OFF_A1;
    float*    A2   = sm + OFF_A2;
    float*    SW0  = sm + OFF_SW0;
    float*    SW1  = sm + OFF_SW1;
    float*    SWF  = sm + OFF_SWF;
    float*    XS   = sm + OFF_XS;
    float*    TE   = sm + OFF_TE;
    float*    HT   = sm + OFF_HT;
    float*    TF   = sm + OFF_TF;
    float*    CF   = sm + OFF_CF;
    unsigned* CFu  = reinterpret_cast<unsigned*>(CF);

    const int tid = threadIdx.x;
    const int r0  = blockIdx.x * BR;

    // ---- one-time staging: x, state (cols 48..175), zero-pad, wf
    for (int idx = tid; idx < BR * 32; idx += NT) {
        int r = idx >> 5, c = idx & 31;
        XS[r * 33 + c] = x_init[(r0 + r) * 32 + c];
    }
    for (int idx = tid; idx < BR * 128; idx += NT) {
        int r = idx >> 7, c = idx & 127;
        A0[r * STA + 48 + c] = state[(r0 + r) * 128 + c];
    }
    for (int idx = tid; idx < BR * 16; idx += NT) {
        int r = idx >> 4, c = idx & 15;
        A0[r * STA + 176 + c] = 0.f;
    }
    for (int idx = tid; idx < 256 * 32; idx += NT) SWF[idx] = wf[idx];
    __syncthreads();

#pragma unroll 1
    for (int i = 999; i >= 0; --i) {
        if (tid == 0) {
            double nn    = (double)(i + 1);
            double ac    = exp(-1e-4 * nn - 4.95e-6 * nn * nn);
            double nm    = nn - 1.0;
            double acp   = (i == 0) ? 1.0 : exp(-1e-4 * nm - 4.95e-6 * nm * nm);
            double beta  = 1.0 - exp(-1e-4 - 4.95e-6 * (2.0 * nn - 1.0));
            double alpha = 1.0 - beta;
            CF[0] = (float)sqrt(1.0 / ac);
            CF[1] = (float)sqrt(1.0 / ac - 1.0);
            CF[2] = (float)(beta * sqrt(acp) / (1.0 - ac));
            CF[3] = (float)((1.0 - acp) * sqrt(alpha) / (1.0 - ac));
            double pv = beta * (1.0 - acp) / (1.0 - ac);
            if (pv < 1e-20) pv = 1e-20;
            float lv = (float)log(pv);
            CF[4] = (float)exp((double)(0.5f * lv));
            unsigned a0 = 0u, a1 = (unsigned)i;
            threefry2x32(0u, 1u, a0, a1);
            CFu[5] = a0; CFu[6] = a1;
        }
        if (tid < 8) {
            float c8   = (float)(-9.210340371976184 / 7.0);
            float freq = expf(c8 * (float)tid);
            float ang  = (float)i * freq;
            TE[tid]     = (float)sin((double)ang);
            TE[tid + 8] = (float)cos((double)ang);
        }
        __syncthreads();
        if (tid < 32) {
            float h = b_t1[tid];
#pragma unroll
            for (int k = 0; k < 16; ++k) h = fmaf(TE[k], w_t1[k * 32 + tid], h);
            HT[tid] = mish_f(h);
        }
        __syncthreads();
        if (tid < 16) {
            float v = b_t2[tid];
#pragma unroll
            for (int k = 0; k < 32; ++k) v = fmaf(HT[k], w_t2[k * 16 + tid], v);
            TF[tid] = v;
        }
        __syncthreads();
        // fill layer-0 input: x cols [0,32), tf cols [32,48)
        for (int idx = tid; idx < BR * 32; idx += NT) {
            int r = idx >> 5, c = idx & 31;
            A0[r * STA + c] = XS[r * 33 + c];
        }
        for (int idx = tid; idx < BR * 16; idx += NT) {
            int r = idx >> 4, c = idx & 15;
            A0[r * STA + 32 + c] = TF[c];
        }
        // dense_layer's first internal __syncthreads covers the fills above

        dense_layer<192, 176, true>(w0, b0, A0, A1, SW0, SW1, tid);
        dense_layer<256, 256, true>(w1, b1, A1, A2, SW0, SW1, tid);
        dense_layer<256, 256, true>(w2, b2, A2, A1, SW0, SW1, tid);
        __syncthreads();

        // ---- final 256 -> 32 : thread = (row = tid>>4, 2 cols at (tid&15)*2)
        const int row = tid >> 4;
        const int cp  = tid & 15;
        unsigned long long f0 = 0ull;
        const float* inr = A1 + row * STA;
#pragma unroll 4
        for (int k4 = 0; k4 < 256; k4 += 4) {
            float4 a4 = *reinterpret_cast<const float4*>(inr + k4);
#pragma unroll
            for (int kk = 0; kk < 4; ++kk) {
                const float* wp = SWF + ((k4 + kk) << 5) + (cp << 1);
                unsigned long long w01 = *reinterpret_cast<const unsigned long long*>(wp);
                float a = reinterpret_cast<const float*>(&a4)[kk];
                unsigned long long aa;
                PACK_DUP(aa, a);
                FMA2(f0, aa, w01);
            }
        }
        float e0, e1;
        UNPACK2(e0, e1, f0);
        float eps[2] = { e0 + bf[cp * 2], e1 + bf[cp * 2 + 1] };

        float sr = CF[0], srm1 = CF[1], c1 = CF[2], c2 = CF[3], sig = CF[4];
        unsigned fk0 = CFu[5], fk1 = CFu[6];

        const int R = r0 + row;
#pragma unroll
        for (int cc = 0; cc < 2; ++cc) {
            int   j  = (cp << 1) + cc;
            float xv = XS[row * 33 + j];
            float x0 = fminf(1.f, fmaxf(-1.f, sr * xv - srm1 * eps[cc]));
            float mean = c1 * x0 + c2 * xv;
            if (i != 0) {
                unsigned f = (unsigned)(R * 32 + j);
                unsigned b0r = 0u, b1r = f;
                threefry2x32(fk0, fk1, b0r, b1r);
                unsigned bits = b0r ^ b1r;
                float fv = __uint_as_float((bits >> 9) | 0x3f800000u) - 1.0f;
                const float lo = -0.99999994f;
                float u   = fmaxf(lo, fmaf(fv, 2.0f, lo));
                float nrm = 1.4142135623730951f * erfinv_xla(u);
                XS[row * 33 + j] = mean + sig * nrm;
            } else {
                float xf = fminf(1.f, fmaxf(-1.f, mean));
                XS[row * 33 + j] = xf;
                outp[R * 32 + j] = xf;
            }
        }
        __syncthreads();
    }
}

extern "C" void kernel_launch(void* const* d_in, const int* in_sizes, int n_in,
                              void* d_out, int out_size) {
    const float* state = (const float*)d_in[0];
    const float* xinit = (const float*)d_in[1];
    const float* w_t1  = (const float*)d_in[2];
    const float* b_t1  = (const float*)d_in[3];
    const float* w_t2  = (const float*)d_in[4];
    const float* b_t2  = (const float*)d_in[5];
    const float* w0    = (const float*)d_in[6];
    const float* b0    = (const float*)d_in[7];
    const float* w1    = (const float*)d_in[8];
    const float* b1    = (const float*)d_in[9];
    const float* w2    = (const float*)d_in[10];
    const float* b2    = (const float*)d_in[11];
    const float* wf    = (const float*)d_in[12];
    const float* bf    = (const float*)d_in[13];
    float* outp = (float*)d_out;

    cudaFuncSetAttribute(diff_all, cudaFuncAttributeMaxDynamicSharedMemorySize, SMEM_BYTES);

    diff_all<<<NB, NT, SMEM_BYTES>>>(state, xinit,
        w_t1, b_t1, w_t2, b_t2,
        w0, b0, w1, b1, w2, b2, wf, bf, outp);
}

// round 7
// speedup vs baseline: 1.4008x; 1.4008x over previous
#include <cuda_runtime.h>
#include <cuda_bf16.h>
#include <math.h>

#define NB 128
#define NT 256
#define BR 32
#define A0S 200      // layer-0 activation row stride (bf16 units), K=192 used
#define AS  264      // 256-wide activation row stride (bf16 units) — 528B, LDSM conflict-free
#define WS  264      // weight chunk row stride (bf16 units)

// ---- smem layout ----
// float region (offsets in floats)
#define F_SWF 0                    // 256*32 fp32 final weights
#define F_XS  8192                 // 32*33 fp32 x state
#define F_TE  9248
#define F_HT  9264
#define F_TF  9296
#define F_CF  9312                 // 16 floats scalars
// bf16 region (offsets in bf16 units, base byte 37376 = unit 18688)
#define B_A0H 18688                // 32*200
#define B_A0L 25088
#define B_A1H 31488                // 32*264
#define B_A1L 39936
#define B_A2H 48384
#define B_A2L 56832
#define B_SW0H 65280               // 32*264 weight chunk buffers
#define B_SW0L 73728
#define B_SW1H 82176
#define B_SW1L 90624
#define SMEM_BYTES 198144

// pre-split weights (bf16 hi/lo), layout [k][n] n-contiguous; w0 k-padded to 192
#define W0_OFF 0
#define W1_OFF (192*256)
#define W2_OFF (192*256 + 256*256)
#define W_TOT  (192*256 + 256*256 + 256*256)
__device__ __nv_bfloat16 g_whi[W_TOT];
__device__ __nv_bfloat16 g_wlo[W_TOT];

// ---- packed f32x2 helpers (final layer) ------------------------------------
#define FMA2(acc, aa, bb) \
    asm("fma.rn.f32x2 %0, %1, %2, %0;" : "+l"(acc) : "l"(aa), "l"(bb))
#define PACK_DUP(dst, fv) do { \
    unsigned _pi = __float_as_uint(fv); \
    asm("mov.b64 %0, {%1, %1};" : "=l"(dst) : "r"(_pi)); } while (0)
#define UNPACK2(lo, hi, src) do { \
    unsigned _u0, _u1; \
    asm("mov.b64 {%0, %1}, %2;" : "=r"(_u0), "=r"(_u1) : "l"(src)); \
    lo = __uint_as_float(_u0); hi = __uint_as_float(_u1); } while (0)

// ---------------- threefry2x32-20 (exact JAX) ------------------------------
__device__ __forceinline__ unsigned rotl32(unsigned x, int r) {
    return __funnelshift_l(x, x, r);
}
__device__ __forceinline__ void threefry2x32(unsigned k0, unsigned k1,
                                             unsigned &x0, unsigned &x1) {
    unsigned k2 = k0 ^ k1 ^ 0x1BD11BDAu;
#define TFR(r) { x0 += x1; x1 = rotl32(x1, r); x1 ^= x0; }
    x0 += k0; x1 += k1;
    TFR(13) TFR(15) TFR(26) TFR(6)
    x0 += k1; x1 += k2 + 1u;
    TFR(17) TFR(29) TFR(16) TFR(24)
    x0 += k2; x1 += k0 + 2u;
    TFR(13) TFR(15) TFR(26) TFR(6)
    x0 += k0; x1 += k1 + 3u;
    TFR(17) TFR(29) TFR(16) TFR(24)
    x0 += k1; x1 += k2 + 4u;
    TFR(13) TFR(15) TFR(26) TFR(6)
    x0 += k2; x1 += k0 + 5u;
#undef TFR
}

// ---------------- XLA ErfInv f32 (Giles) ------------------------------------
__device__ __forceinline__ float erfinv_xla(float x) {
    float w = -log1pf(-x * x);
    float p;
    if (w < 5.0f) {
        w -= 2.5f;
        p = 2.81022636e-08f;
        p = fmaf(p, w, 3.43273939e-07f);
        p = fmaf(p, w, -3.5233877e-06f);
        p = fmaf(p, w, -4.39150654e-06f);
        p = fmaf(p, w, 0.00021858087f);
        p = fmaf(p, w, -0.00125372503f);
        p = fmaf(p, w, -0.00417768164f);
        p = fmaf(p, w, 0.246640727f);
        p = fmaf(p, w, 1.50140941f);
    } else {
        w = sqrtf(w) - 3.0f;
        p = -0.000200214257f;
        p = fmaf(p, w, 0.000100950558f);
        p = fmaf(p, w, 0.00134934322f);
        p = fmaf(p, w, -0.00367342844f);
        p = fmaf(p, w, 0.00573950773f);
        p = fmaf(p, w, -0.0076224613f);
        p = fmaf(p, w, 0.00943887047f);
        p = fmaf(p, w, 1.00167406f);
        p = fmaf(p, w, 2.83297682f);
    }
    return p * x;
}

__device__ __forceinline__ float mish_f(float x) {
    if (x > 20.0f) return x;
    float u = expf(x);
    float s = u * (u + 2.0f);
    return x * (s / (s + 2.0f));
}

// ---------------- cp.async helpers ------------------------------------------
__device__ __forceinline__ void cp16b(__nv_bfloat16* dst, const __nv_bfloat16* src) {
    unsigned sa = (unsigned)__cvta_generic_to_shared(dst);
    asm volatile("cp.async.cg.shared.global [%0], [%1], 16;\n" :: "r"(sa), "l"(src));
}
#define CP_COMMIT() asm volatile("cp.async.commit_group;\n" ::: "memory")
#define CP_WAIT(n)  asm volatile("cp.async.wait_group %0;\n" :: "n"(n) : "memory")

// stage one 32x256 bf16 weight chunk (hi+lo) into strided smem buffers
__device__ __forceinline__ void stage_w(__nv_bfloat16* dh, __nv_bfloat16* dl,
                                        const __nv_bfloat16* sh,
                                        const __nv_bfloat16* sl, int tid) {
#pragma unroll
    for (int l = 0; l < 4; ++l) {
        int idx = l * NT + tid;       // 1024 16B units
        int row = idx >> 5, u = idx & 31;
        cp16b(dh + row * WS + u * 8, sh + row * 256 + u * 8);
    }
#pragma unroll
    for (int l = 0; l < 4; ++l) {
        int idx = l * NT + tid;
        int row = idx >> 5, u = idx & 31;
        cp16b(dl + row * WS + u * 8, sl + row * 256 + u * 8);
    }
}

// ---------------- mma / ldmatrix wrappers ------------------------------------
__device__ __forceinline__ void mma_bf16(float* c, const unsigned* a,
                                         unsigned b0, unsigned b1) {
    asm volatile(
        "mma.sync.aligned.m16n8k16.row.col.f32.bf16.bf16.f32 "
        "{%0,%1,%2,%3}, {%4,%5,%6,%7}, {%8,%9}, {%0,%1,%2,%3};"
        : "+f"(c[0]), "+f"(c[1]), "+f"(c[2]), "+f"(c[3])
        : "r"(a[0]), "r"(a[1]), "r"(a[2]), "r"(a[3]), "r"(b0), "r"(b1));
}
__device__ __forceinline__ void ldsm4t(unsigned* r, const __nv_bfloat16* p) {
    unsigned addr = (unsigned)__cvta_generic_to_shared(p);
    asm volatile("ldmatrix.sync.aligned.m8n8.x4.trans.shared.b16 {%0,%1,%2,%3}, [%4];"
        : "=r"(r[0]), "=r"(r[1]), "=r"(r[2]), "=r"(r[3]) : "r"(addr));
}

// split fp32 -> bf16 hi/lo, store a contiguous pair as one u32 each
__device__ __forceinline__ void store_split2(__nv_bfloat16* H, __nv_bfloat16* L,
                                             int off, float v0, float v1) {
    __nv_bfloat16 h0 = __float2bfloat16(v0), h1 = __float2bfloat16(v1);
    __nv_bfloat16 l0 = __float2bfloat16(v0 - __bfloat162float(h0));
    __nv_bfloat16 l1 = __float2bfloat16(v1 - __bfloat162float(h1));
    *reinterpret_cast<unsigned*>(H + off) =
        (unsigned)__bfloat16_as_ushort(h0) | ((unsigned)__bfloat16_as_ushort(h1) << 16);
    *reinterpret_cast<unsigned*>(L + off) =
        (unsigned)__bfloat16_as_ushort(l0) | ((unsigned)__bfloat16_as_ushort(l1) << 16);
}

// ---------------- split-bf16 dense layer: [32,K] x [K,256] -> [32,256] -------
template <int NCH, int INS>
__device__ __forceinline__ void gemm_layer(const __nv_bfloat16* __restrict__ Wh,
                                           const __nv_bfloat16* __restrict__ Wl,
                                           const float* __restrict__ bias,
                                           const __nv_bfloat16* INh,
                                           const __nv_bfloat16* INl,
                                           __nv_bfloat16* OUTh, __nv_bfloat16* OUTl,
                                           __nv_bfloat16* SW0h, __nv_bfloat16* SW0l,
                                           __nv_bfloat16* SW1h, __nv_bfloat16* SW1l,
                                           int tid) {
    const int lane = tid & 31, w = tid >> 5;
    const int g = lane >> 2, t = lane & 3;
    const int mrow = (w & 1) << 4;      // 0 or 16
    const int q = w >> 1;               // 0..3 -> cols 64q..64q+63
    const int krow_l = (lane & 7) + ((lane >> 3) & 1) * 8;
    const int nc_l = (lane >> 4) * 8;

    float acc[8][4];
#pragma unroll
    for (int i = 0; i < 8; ++i)
#pragma unroll
        for (int j = 0; j < 4; ++j) acc[i][j] = 0.f;

    stage_w(SW0h, SW0l, Wh, Wl, tid);
    CP_COMMIT();

#pragma unroll 1
    for (int c = 0; c < NCH; ++c) {
        if (c + 1 < NCH) {
            stage_w((c & 1) ? SW0h : SW1h, (c & 1) ? SW0l : SW1l,
                    Wh + (c + 1) * 32 * 256, Wl + (c + 1) * 32 * 256, tid);
            CP_COMMIT(); CP_WAIT(1);
        } else {
            CP_WAIT(0);
        }
        __syncthreads();
        const __nv_bfloat16* swh = (c & 1) ? SW1h : SW0h;
        const __nv_bfloat16* swl = (c & 1) ? SW1l : SW0l;
#pragma unroll
        for (int kk = 0; kk < 2; ++kk) {
            const int kg = c * 32 + kk * 16;
            const __nv_bfloat16* ah_p = INh + (mrow + g) * INS + kg + 2 * t;
            const __nv_bfloat16* al_p = INl + (mrow + g) * INS + kg + 2 * t;
            unsigned ah[4], al[4];
            ah[0] = *reinterpret_cast<const unsigned*>(ah_p);
            ah[1] = *reinterpret_cast<const unsigned*>(ah_p + 8 * INS);
            ah[2] = *reinterpret_cast<const unsigned*>(ah_p + 8);
            ah[3] = *reinterpret_cast<const unsigned*>(ah_p + 8 * INS + 8);
            al[0] = *reinterpret_cast<const unsigned*>(al_p);
            al[1] = *reinterpret_cast<const unsigned*>(al_p + 8 * INS);
            al[2] = *reinterpret_cast<const unsigned*>(al_p + 8);
            al[3] = *reinterpret_cast<const unsigned*>(al_p + 8 * INS + 8);
            const int krow = kk * 16 + krow_l;
#pragma unroll
            for (int p = 0; p < 4; ++p) {
                const int ncol = (q << 6) + (p << 4) + nc_l;
                unsigned bh[4], bl[4];
                ldsm4t(bh, swh + krow * WS + ncol);
                ldsm4t(bl, swl + krow * WS + ncol);
                mma_bf16(acc[2 * p],     ah, bh[0], bh[1]);
                mma_bf16(acc[2 * p],     ah, bl[0], bl[1]);
                mma_bf16(acc[2 * p],     al, bh[0], bh[1]);
                mma_bf16(acc[2 * p + 1], ah, bh[2], bh[3]);
                mma_bf16(acc[2 * p + 1], ah, bl[2], bl[3]);
                mma_bf16(acc[2 * p + 1], al, bh[2], bh[3]);
            }
        }
        __syncthreads();
    }

    // epilogue: bias + mish, split-store
#pragma unroll
    for (int nt = 0; nt < 8; ++nt) {
        const int col = (q << 6) + (nt << 3) + 2 * t;
        float b0v = bias[col], b1v = bias[col + 1];
        float v00 = mish_f(acc[nt][0] + b0v);
        float v01 = mish_f(acc[nt][1] + b1v);
        float v10 = mish_f(acc[nt][2] + b0v);
        float v11 = mish_f(acc[nt][3] + b1v);
        store_split2(OUTh, OUTl, (mrow + g) * AS + col, v00, v01);
        store_split2(OUTh, OUTl, (mrow + g + 8) * AS + col, v10, v11);
    }
}

// ---------------- init: split fp32 weights -> global bf16 hi/lo --------------
__global__ void split_weights(const float* __restrict__ w0,
                              const float* __restrict__ w1,
                              const float* __restrict__ w2) {
    int idx = blockIdx.x * blockDim.x + threadIdx.x;
    if (idx >= W_TOT) return;
    float v;
    if (idx < W1_OFF) {
        int k = idx >> 8, n = idx & 255;
        v = (k < 176) ? w0[k * 256 + n] : 0.f;
    } else if (idx < W2_OFF) {
        v = w1[idx - W1_OFF];
    } else {
        v = w2[idx - W2_OFF];
    }
    __nv_bfloat16 hi = __float2bfloat16(v);
    __nv_bfloat16 lo = __float2bfloat16(v - __bfloat162float(hi));
    g_whi[idx] = hi;
    g_wlo[idx] = lo;
}

// ---------------- persistent sampler -----------------------------------------
__global__ void __launch_bounds__(NT, 1)
diff_all(const float* __restrict__ state, const float* __restrict__ x_init,
         const float* __restrict__ w_t1, const float* __restrict__ b_t1,
         const float* __restrict__ w_t2, const float* __restrict__ b_t2,
         const float* __restrict__ b0,  const float* __restrict__ b1,
         const float* __restrict__ b2,
         const float* __restrict__ wf,  const float* __restrict__ bf,
         float* __restrict__ outp)
{
    extern __shared__ char smraw[];
    float* smf = reinterpret_cast<float*>(smraw);
    __nv_bfloat16* smb = reinterpret_cast<__nv_bfloat16*>(smraw);

    float* SWF = smf + F_SWF;
    float* XS  = smf + F_XS;
    float* TE  = smf + F_TE;
    float* HT  = smf + F_HT;
    float* TF  = smf + F_TF;
    float* CF  = smf + F_CF;
    unsigned* CFu = reinterpret_cast<unsigned*>(CF);

    __nv_bfloat16* A0h = smb + B_A0H;  __nv_bfloat16* A0l = smb + B_A0L;
    __nv_bfloat16* A1h = smb + B_A1H;  __nv_bfloat16* A1l = smb + B_A1L;
    __nv_bfloat16* A2h = smb + B_A2H;  __nv_bfloat16* A2l = smb + B_A2L;
    __nv_bfloat16* SW0h = smb + B_SW0H; __nv_bfloat16* SW0l = smb + B_SW0L;
    __nv_bfloat16* SW1h = smb + B_SW1H; __nv_bfloat16* SW1l = smb + B_SW1L;

    const int tid = threadIdx.x;
    const int r0  = blockIdx.x * BR;

    // ---- one-time staging
    for (int idx = tid; idx < BR * 32; idx += NT) {
        int r = idx >> 5, c = idx & 31;
        XS[r * 33 + c] = x_init[(r0 + r) * 32 + c];
    }
    for (int idx = tid; idx < BR * 128; idx += NT) {          // state -> A0 cols 48..175
        int r = idx >> 7, c = idx & 127;
        float v = state[(r0 + r) * 128 + c];
        __nv_bfloat16 hi = __float2bfloat16(v);
        __nv_bfloat16 lo = __float2bfloat16(v - __bfloat162float(hi));
        A0h[r * A0S + 48 + c] = hi;
        A0l[r * A0S + 48 + c] = lo;
    }
    for (int idx = tid; idx < BR * 16; idx += NT) {           // zero pad cols 176..191
        int r = idx >> 4, c = idx & 15;
        __nv_bfloat16 z = __float2bfloat16(0.f);
        A0h[r * A0S + 176 + c] = z;
        A0l[r * A0S + 176 + c] = z;
    }
    for (int idx = tid; idx < 256 * 32; idx += NT) SWF[idx] = wf[idx];
    __syncthreads();

#pragma unroll 1
    for (int i = 999; i >= 0; --i) {
        if (tid == 0) {
            double nn    = (double)(i + 1);
            double ac    = exp(-1e-4 * nn - 4.95e-6 * nn * nn);
            double nm    = nn - 1.0;
            double acp   = (i == 0) ? 1.0 : exp(-1e-4 * nm - 4.95e-6 * nm * nm);
            double beta  = 1.0 - exp(-1e-4 - 4.95e-6 * (2.0 * nn - 1.0));
            double alpha = 1.0 - beta;
            CF[0] = (float)sqrt(1.0 / ac);
            CF[1] = (float)sqrt(1.0 / ac - 1.0);
            CF[2] = (float)(beta * sqrt(acp) / (1.0 - ac));
            CF[3] = (float)((1.0 - acp) * sqrt(alpha) / (1.0 - ac));
            double pv = beta * (1.0 - acp) / (1.0 - ac);
            if (pv < 1e-20) pv = 1e-20;
            float lv = (float)log(pv);
            CF[4] = (float)exp((double)(0.5f * lv));
            unsigned a0 = 0u, a1 = (unsigned)i;
            threefry2x32(0u, 1u, a0, a1);
            CFu[5] = a0; CFu[6] = a1;
        }
        if (tid < 8) {
            float c8   = (float)(-9.210340371976184 / 7.0);
            float freq = expf(c8 * (float)tid);
            float ang  = (float)i * freq;
            TE[tid]     = (float)sin((double)ang);
            TE[tid + 8] = (float)cos((double)ang);
        }
        __syncthreads();
        if (tid < 32) {
            float h = b_t1[tid];
#pragma unroll
            for (int k = 0; k < 16; ++k) h = fmaf(TE[k], w_t1[k * 32 + tid], h);
            HT[tid] = mish_f(h);
        }
        __syncthreads();
        if (tid < 16) {
            float v = b_t2[tid];
#pragma unroll
            for (int k = 0; k < 32; ++k) v = fmaf(HT[k], w_t2[k * 16 + tid], v);
            TF[tid] = v;
        }
        __syncthreads();
        // refresh A0 cols 0..47 (x and tf), split to bf16 hi/lo
        for (int idx = tid; idx < 32 * 48; idx += NT) {
            int r = idx & 31, c = idx >> 5;     // c = 0..47
            float v = (c < 32) ? XS[r * 33 + c] : TF[c - 32];
            __nv_bfloat16 hi = __float2bfloat16(v);
            __nv_bfloat16 lo = __float2bfloat16(v - __bfloat162float(hi));
            A0h[r * A0S + c] = hi;
            A0l[r * A0S + c] = lo;
        }
        // gemm_layer's first internal __syncthreads covers the refresh

        gemm_layer<6, A0S>(g_whi + W0_OFF, g_wlo + W0_OFF, b0, A0h, A0l,
                           A1h, A1l, SW0h, SW0l, SW1h, SW1l, tid);
        gemm_layer<8, AS >(g_whi + W1_OFF, g_wlo + W1_OFF, b1, A1h, A1l,
                           A2h, A2l, SW0h, SW0l, SW1h, SW1l, tid);
        gemm_layer<8, AS >(g_whi + W2_OFF, g_wlo + W2_OFF, b2, A2h, A2l,
                           A1h, A1l, SW0h, SW0l, SW1h, SW1l, tid);
        __syncthreads();

        // ---- final 256 -> 32 (exact fp32): row = tid>>3, 4 cols at (tid&7)*4
        const int row = tid >> 3;
        const int cg  = tid & 7;
        unsigned long long f0 = 0ull, f1 = 0ull;
        const __nv_bfloat16* inh = A1h + row * AS;
        const __nv_bfloat16* inl = A1l + row * AS;
#pragma unroll 4
        for (int k2 = 0; k2 < 256; k2 += 2) {
            __nv_bfloat162 ph = *reinterpret_cast<const __nv_bfloat162*>(inh + k2);
            __nv_bfloat162 pl = *reinterpret_cast<const __nv_bfloat162*>(inl + k2);
            float a0 = __bfloat162float(ph.x) + __bfloat162float(pl.x);
            float a1 = __bfloat162float(ph.y) + __bfloat162float(pl.y);
#pragma unroll
            for (int kk = 0; kk < 2; ++kk) {
                float a = kk ? a1 : a0;
                const float* wp = SWF + ((k2 + kk) << 5) + (cg << 2);
                unsigned long long w01 = *reinterpret_cast<const unsigned long long*>(wp);
                unsigned long long w23 = *reinterpret_cast<const unsigned long long*>(wp + 2);
                unsigned long long aa;
                PACK_DUP(aa, a);
                FMA2(f0, aa, w01);
                FMA2(f1, aa, w23);
            }
        }
        float4 bb = *reinterpret_cast<const float4*>(bf + (cg << 2));
        float e0, e1, e2, e3;
        UNPACK2(e0, e1, f0);
        UNPACK2(e2, e3, f1);
        float eps[4] = { e0 + bb.x, e1 + bb.y, e2 + bb.z, e3 + bb.w };

        float sr = CF[0], srm1 = CF[1], c1 = CF[2], c2 = CF[3], sig = CF[4];
        unsigned fk0 = CFu[5], fk1 = CFu[6];

        const int R = r0 + row;
#pragma unroll
        for (int cc = 0; cc < 4; ++cc) {
            int   j  = (cg << 2) + cc;
            float xv = XS[row * 33 + j];
            float x0 = fminf(1.f, fmaxf(-1.f, sr * xv - srm1 * eps[cc]));
            float mean = c1 * x0 + c2 * xv;
            if (i != 0) {
                unsigned f = (unsigned)(R * 32 + j);
                unsigned b0r = 0u, b1r = f;
                threefry2x32(fk0, fk1, b0r, b1r);
                unsigned bits = b0r ^ b1r;
                float fv = __uint_as_float((bits >> 9) | 0x3f800000u) - 1.0f;
                const float lo = -0.99999994f;
                float u   = fmaxf(lo, fmaf(fv, 2.0f, lo));
                float nrm = 1.4142135623730951f * erfinv_xla(u);
                XS[row * 33 + j] = mean + sig * nrm;
            } else {
                float xf = fminf(1.f, fmaxf(-1.f, mean));
                XS[row * 33 + j] = xf;
                outp[R * 32 + j] = xf;
            }
        }
        __syncthreads();
    }
}

extern "C" void kernel_launch(void* const* d_in, const int* in_sizes, int n_in,
                              void* d_out, int out_size) {
    const float* state = (const float*)d_in[0];
    const float* xinit = (const float*)d_in[1];
    const float* w_t1  = (const float*)d_in[2];
    const float* b_t1  = (const float*)d_in[3];
    const float* w_t2  = (const float*)d_in[4];
    const float* b_t2  = (const float*)d_in[5];
    const float* w0    = (const float*)d_in[6];
    const float* b0    = (const float*)d_in[7];
    const float* w1    = (const float*)d_in[8];
    const float* b1    = (const float*)d_in[9];
    const float* w2    = (const float*)d_in[10];
    const float* b2    = (const float*)d_in[11];
    const float* wf    = (const float*)d_in[12];
    const float* bf    = (const float*)d_in[13];
    float* outp = (float*)d_out;

    cudaFuncSetAttribute(diff_all, cudaFuncAttributeMaxDynamicSharedMemorySize, SMEM_BYTES);

    split_weights<<<(W_TOT + 255) / 256, 256>>>(w0, w1, w2);
    diff_all<<<NB, NT, SMEM_BYTES>>>(state, xinit,
        w_t1, b_t1, w_t2, b_t2,
        b0, b1, b2, wf, bf, outp);
}

// round 8
// speedup vs baseline: 1.4189x; 1.0130x over previous
#include <cuda_runtime.h>
#include <cuda_bf16.h>
#include <math.h>

#define NB 128
#define NT 512
#define BR 32
#define AS  264     // activation & weight-chunk row stride (bf16 units) = 528B
#define WS  264

// ---- smem layout ----
// float region (offsets in floats)
#define F_SWF 0                    // 256*32 fp32 final weights
#define F_XS  8192                 // 32*33
#define F_TE  9248
#define F_HT  9264
#define F_TF  9296
#define F_CF  9312
// bf16 region (offsets in bf16 units; base = 2*9328 = 18656)
#define B_A0H 18656                // 32*264 (A2 aliases A0)
#define B_A0L 27104
#define B_A1H 35552
#define B_A1L 44000
#define B_SW0H 52448
#define B_SW0L 60896
#define B_SW1H 69344
#define B_SW1L 77792
#define B_SW2H 86240
#define B_SW2L 94688
#define SMEM_BYTES 206272

// pre-split weights (bf16 hi/lo), layout [k][n]; w0 k-padded to 192
#define W0_OFF 0
#define W1_OFF (192*256)
#define W2_OFF (192*256 + 256*256)
#define W_TOT  (192*256 + 256*256 + 256*256)
__device__ __nv_bfloat16 g_whi[W_TOT];
__device__ __nv_bfloat16 g_wlo[W_TOT];

// ---- packed f32x2 helpers (final layer) ------------------------------------
#define FMA2(acc, aa, bb) \
    asm("fma.rn.f32x2 %0, %1, %2, %0;" : "+l"(acc) : "l"(aa), "l"(bb))
#define PACK_DUP(dst, fv) do { \
    unsigned _pi = __float_as_uint(fv); \
    asm("mov.b64 %0, {%1, %1};" : "=l"(dst) : "r"(_pi)); } while (0)
#define UNPACK2(lo, hi, src) do { \
    unsigned _u0, _u1; \
    asm("mov.b64 {%0, %1}, %2;" : "=r"(_u0), "=r"(_u1) : "l"(src)); \
    lo = __uint_as_float(_u0); hi = __uint_as_float(_u1); } while (0)

// ---------------- threefry2x32-20 (exact JAX) ------------------------------
__device__ __forceinline__ unsigned rotl32(unsigned x, int r) {
    return __funnelshift_l(x, x, r);
}
__device__ __forceinline__ void threefry2x32(unsigned k0, unsigned k1,
                                             unsigned &x0, unsigned &x1) {
    unsigned k2 = k0 ^ k1 ^ 0x1BD11BDAu;
#define TFR(r) { x0 += x1; x1 = rotl32(x1, r); x1 ^= x0; }
    x0 += k0; x1 += k1;
    TFR(13) TFR(15) TFR(26) TFR(6)
    x0 += k1; x1 += k2 + 1u;
    TFR(17) TFR(29) TFR(16) TFR(24)
    x0 += k2; x1 += k0 + 2u;
    TFR(13) TFR(15) TFR(26) TFR(6)
    x0 += k0; x1 += k1 + 3u;
    TFR(17) TFR(29) TFR(16) TFR(24)
    x0 += k1; x1 += k2 + 4u;
    TFR(13) TFR(15) TFR(26) TFR(6)
    x0 += k2; x1 += k0 + 5u;
#undef TFR
}

// ---------------- XLA ErfInv f32 (Giles) ------------------------------------
__device__ __forceinline__ float erfinv_xla(float x) {
    float w = -log1pf(-x * x);
    float p;
    if (w < 5.0f) {
        w -= 2.5f;
        p = 2.81022636e-08f;
        p = fmaf(p, w, 3.43273939e-07f);
        p = fmaf(p, w, -3.5233877e-06f);
        p = fmaf(p, w, -4.39150654e-06f);
        p = fmaf(p, w, 0.00021858087f);
        p = fmaf(p, w, -0.00125372503f);
        p = fmaf(p, w, -0.00417768164f);
        p = fmaf(p, w, 0.246640727f);
        p = fmaf(p, w, 1.50140941f);
    } else {
        w = sqrtf(w) - 3.0f;
        p = -0.000200214257f;
        p = fmaf(p, w, 0.000100950558f);
        p = fmaf(p, w, 0.00134934322f);
        p = fmaf(p, w, -0.00367342844f);
        p = fmaf(p, w, 0.00573950773f);
        p = fmaf(p, w, -0.0076224613f);
        p = fmaf(p, w, 0.00943887047f);
        p = fmaf(p, w, 1.00167406f);
        p = fmaf(p, w, 2.83297682f);
    }
    return p * x;
}

__device__ __forceinline__ float mish_f(float x) {
    if (x > 20.0f) return x;
    float u = expf(x);
    float s = u * (u + 2.0f);
    return x * (s / (s + 2.0f));
}

// ---------------- cp.async helpers ------------------------------------------
__device__ __forceinline__ void cp16b(__nv_bfloat16* dst, const __nv_bfloat16* src) {
    unsigned sa = (unsigned)__cvta_generic_to_shared(dst);
    asm volatile("cp.async.cg.shared.global [%0], [%1], 16;\n" :: "r"(sa), "l"(src));
}
#define CP_COMMIT() asm volatile("cp.async.commit_group;\n" ::: "memory")
#define CP_WAIT(n)  asm volatile("cp.async.wait_group %0;\n" :: "n"(n) : "memory")

// stage one 32x256 bf16 chunk (hi+lo); NT=512 -> 2+2 cp.async per thread
__device__ __forceinline__ void stage_w(__nv_bfloat16* dh, __nv_bfloat16* dl,
                                        const __nv_bfloat16* sh,
                                        const __nv_bfloat16* sl, int tid) {
#pragma unroll
    for (int l = 0; l < 2; ++l) {
        int idx = l * NT + tid;       // 1024 16B units
        int row = idx >> 5, u = idx & 31;
        cp16b(dh + row * WS + u * 8, sh + row * 256 + u * 8);
    }
#pragma unroll
    for (int l = 0; l < 2; ++l) {
        int idx = l * NT + tid;
        int row = idx >> 5, u = idx & 31;
        cp16b(dl + row * WS + u * 8, sl + row * 256 + u * 8);
    }
}

// ---------------- mma / ldmatrix wrappers ------------------------------------
__device__ __forceinline__ void mma_bf16(float* c, const unsigned* a,
                                         unsigned b0, unsigned b1) {
    asm volatile(
        "mma.sync.aligned.m16n8k16.row.col.f32.bf16.bf16.f32 "
        "{%0,%1,%2,%3}, {%4,%5,%6,%7}, {%8,%9}, {%0,%1,%2,%3};"
        : "+f"(c[0]), "+f"(c[1]), "+f"(c[2]), "+f"(c[3])
        : "r"(a[0]), "r"(a[1]), "r"(a[2]), "r"(a[3]), "r"(b0), "r"(b1));
}
__device__ __forceinline__ void ldsm4t(unsigned* r, const __nv_bfloat16* p) {
    unsigned addr = (unsigned)__cvta_generic_to_shared(p);
    asm volatile("ldmatrix.sync.aligned.m8n8.x4.trans.shared.b16 {%0,%1,%2,%3}, [%4];"
        : "=r"(r[0]), "=r"(r[1]), "=r"(r[2]), "=r"(r[3]) : "r"(addr));
}

__device__ __forceinline__ void store_split2(__nv_bfloat16* H, __nv_bfloat16* L,
                                             int off, float v0, float v1) {
    __nv_bfloat16 h0 = __float2bfloat16(v0), h1 = __float2bfloat16(v1);
    __nv_bfloat16 l0 = __float2bfloat16(v0 - __bfloat162float(h0));
    __nv_bfloat16 l1 = __float2bfloat16(v1 - __bfloat162float(h1));
    *reinterpret_cast<unsigned*>(H + off) =
        (unsigned)__bfloat16_as_ushort(h0) | ((unsigned)__bfloat16_as_ushort(h1) << 16);
    *reinterpret_cast<unsigned*>(L + off) =
        (unsigned)__bfloat16_as_ushort(l0) | ((unsigned)__bfloat16_as_ushort(l1) << 16);
}

// ------- split-bf16 dense layer: [32,K]x[K,256] -> [32,256], 16 warps --------
// 3-buffer ring, ONE __syncthreads per chunk (+1 entry sync).
template <int NCH>
__device__ __forceinline__ void gemm_layer(const __nv_bfloat16* __restrict__ Wh,
                                           const __nv_bfloat16* __restrict__ Wl,
                                           const float* __restrict__ bias,
                                           const __nv_bfloat16* INh,
                                           const __nv_bfloat16* INl,
                                           __nv_bfloat16* OUTh, __nv_bfloat16* OUTl,
                                           __nv_bfloat16* const* SBh,
                                           __nv_bfloat16* const* SBl, int tid) {
    const int lane = tid & 31, w = tid >> 5;    // 16 warps
    const int g = lane >> 2, t = lane & 3;
    const int mrow = (w & 1) << 4;              // 0 or 16
    const int q = w >> 1;                        // 0..7 -> cols 32q..32q+31
    const int krow_l = (lane & 7) + ((lane >> 3) & 1) * 8;
    const int nc_l = (lane >> 4) * 8;

    float acc[4][4];
#pragma unroll
    for (int i = 0; i < 4; ++i)
#pragma unroll
        for (int j = 0; j < 4; ++j) acc[i][j] = 0.f;

    __syncthreads();                 // prev layer's reads/writes of smem done
    stage_w(SBh[0], SBl[0], Wh, Wl, tid);
    CP_COMMIT();

#pragma unroll 1
    for (int c = 0; c < NCH; ++c) {
        if (c + 1 < NCH) {
            int nb = (c + 1) % 3;
            stage_w(SBh[nb], SBl[nb],
                    Wh + (c + 1) * 32 * 256, Wl + (c + 1) * 32 * 256, tid);
            CP_COMMIT(); CP_WAIT(1);
        } else {
            CP_WAIT(0);
        }
        __syncthreads();
        const __nv_bfloat16* swh = SBh[c % 3];
        const __nv_bfloat16* swl = SBl[c % 3];
#pragma unroll
        for (int kk = 0; kk < 2; ++kk) {
            const int kg = c * 32 + kk * 16;
            const __nv_bfloat16* ah_p = INh + (mrow + g) * AS + kg + 2 * t;
            const __nv_bfloat16* al_p = INl + (mrow + g) * AS + kg + 2 * t;
            unsigned ah[4], al[4];
            ah[0] = *reinterpret_cast<const unsigned*>(ah_p);
            ah[1] = *reinterpret_cast<const unsigned*>(ah_p + 8 * AS);
            ah[2] = *reinterpret_cast<const unsigned*>(ah_p + 8);
            ah[3] = *reinterpret_cast<const unsigned*>(ah_p + 8 * AS + 8);
            al[0] = *reinterpret_cast<const unsigned*>(al_p);
            al[1] = *reinterpret_cast<const unsigned*>(al_p + 8 * AS);
            al[2] = *reinterpret_cast<const unsigned*>(al_p + 8);
            al[3] = *reinterpret_cast<const unsigned*>(al_p + 8 * AS + 8);
            const int krow = kk * 16 + krow_l;
#pragma unroll
            for (int p = 0; p < 2; ++p) {
                const int ncol = (q << 5) + (p << 4) + nc_l;
                unsigned bh[4], bl[4];
                ldsm4t(bh, swh + krow * WS + ncol);
                ldsm4t(bl, swl + krow * WS + ncol);
                mma_bf16(acc[2 * p],     ah, bh[0], bh[1]);
                mma_bf16(acc[2 * p],     ah, bl[0], bl[1]);
                mma_bf16(acc[2 * p],     al, bh[0], bh[1]);
                mma_bf16(acc[2 * p + 1], ah, bh[2], bh[3]);
                mma_bf16(acc[2 * p + 1], ah, bl[2], bl[3]);
                mma_bf16(acc[2 * p + 1], al, bh[2], bh[3]);
            }
        }
    }

    // epilogue: bias + mish, split-store (no sync here; next layer entry-syncs)
#pragma unroll
    for (int nt = 0; nt < 4; ++nt) {
        const int col = (q << 5) + (nt << 3) + 2 * t;
        float b0v = bias[col], b1v = bias[col + 1];
        float v00 = mish_f(acc[nt][0] + b0v);
        float v01 = mish_f(acc[nt][1] + b1v);
        float v10 = mish_f(acc[nt][2] + b0v);
        float v11 = mish_f(acc[nt][3] + b1v);
        store_split2(OUTh, OUTl, (mrow + g) * AS + col, v00, v01);
        store_split2(OUTh, OUTl, (mrow + g + 8) * AS + col, v10, v11);
    }
}

// ---------------- init: split fp32 weights -> global bf16 hi/lo --------------
__global__ void split_weights(const float* __restrict__ w0,
                              const float* __restrict__ w1,
                              const float* __restrict__ w2) {
    int idx = blockIdx.x * blockDim.x + threadIdx.x;
    if (idx >= W_TOT) return;
    float v;
    if (idx < W1_OFF) {
        int k = idx >> 8, n = idx & 255;
        v = (k < 176) ? w0[k * 256 + n] : 0.f;
    } else if (idx < W2_OFF) {
        v = w1[idx - W1_OFF];
    } else {
        v = w2[idx - W2_OFF];
    }
    __nv_bfloat16 hi = __float2bfloat16(v);
    __nv_bfloat16 lo = __float2bfloat16(v - __bfloat162float(hi));
    g_whi[idx] = hi;
    g_wlo[idx] = lo;
}

// ---------------- persistent sampler -----------------------------------------
__global__ void __launch_bounds__(NT, 1)
diff_all(const float* __restrict__ state, const float* __restrict__ x_init,
         const float* __restrict__ w_t1, const float* __restrict__ b_t1,
         const float* __restrict__ w_t2, const float* __restrict__ b_t2,
         const float* __restrict__ b0,  const float* __restrict__ b1,
         const float* __restrict__ b2,
         const float* __restrict__ wf,  const float* __restrict__ bf,
         float* __restrict__ outp)
{
    extern __shared__ char smraw[];
    float* smf = reinterpret_cast<float*>(smraw);
    __nv_bfloat16* smb = reinterpret_cast<__nv_bfloat16*>(smraw);

    float* SWF = smf + F_SWF;
    float* XS  = smf + F_XS;
    float* TE  = smf + F_TE;
    float* HT  = smf + F_HT;
    float* TF  = smf + F_TF;
    float* CF  = smf + F_CF;
    unsigned* CFu = reinterpret_cast<unsigned*>(CF);

    __nv_bfloat16* A0h = smb + B_A0H;  __nv_bfloat16* A0l = smb + B_A0L;
    __nv_bfloat16* A1h = smb + B_A1H;  __nv_bfloat16* A1l = smb + B_A1L;
    __nv_bfloat16* SBh[3] = { smb + B_SW0H, smb + B_SW1H, smb + B_SW2H };
    __nv_bfloat16* SBl[3] = { smb + B_SW0L, smb + B_SW1L, smb + B_SW2L };

    const int tid = threadIdx.x;
    const int r0  = blockIdx.x * BR;

    // ---- one-time staging
    for (int idx = tid; idx < BR * 32; idx += NT) {
        int r = idx >> 5, c = idx & 31;
        XS[r * 33 + c] = x_init[(r0 + r) * 32 + c];
    }
    for (int idx = tid; idx < 256 * 32; idx += NT) SWF[idx] = wf[idx];
    __syncthreads();

#pragma unroll 1
    for (int i = 999; i >= 0; --i) {
        if (tid == 0) {
            double nn    = (double)(i + 1);
            double ac    = exp(-1e-4 * nn - 4.95e-6 * nn * nn);
            double nm    = nn - 1.0;
            double acp   = (i == 0) ? 1.0 : exp(-1e-4 * nm - 4.95e-6 * nm * nm);
            double beta  = 1.0 - exp(-1e-4 - 4.95e-6 * (2.0 * nn - 1.0));
            double alpha = 1.0 - beta;
            CF[0] = (float)sqrt(1.0 / ac);
            CF[1] = (float)sqrt(1.0 / ac - 1.0);
            CF[2] = (float)(beta * sqrt(acp) / (1.0 - ac));
            CF[3] = (float)((1.0 - acp) * sqrt(alpha) / (1.0 - ac));
            double pv = beta * (1.0 - acp) / (1.0 - ac);
            if (pv < 1e-20) pv = 1e-20;
            float lv = (float)log(pv);
            CF[4] = (float)exp((double)(0.5f * lv));
            unsigned a0 = 0u, a1 = (unsigned)i;
            threefry2x32(0u, 1u, a0, a1);
            CFu[5] = a0; CFu[6] = a1;
        }
        if (tid < 8) {
            float c8   = (float)(-9.210340371976184 / 7.0);
            float freq = expf(c8 * (float)tid);
            float ang  = (float)i * freq;
            TE[tid]     = (float)sin((double)ang);
            TE[tid + 8] = (float)cos((double)ang);
        }
        __syncthreads();
        if (tid < 32) {
            float h = b_t1[tid];
#pragma unroll
            for (int k = 0; k < 16; ++k) h = fmaf(TE[k], w_t1[k * 32 + tid], h);
            HT[tid] = mish_f(h);
        }
        __syncthreads();
        if (tid < 16) {
            float v = b_t2[tid];
#pragma unroll
            for (int k = 0; k < 32; ++k) v = fmaf(HT[k], w_t2[k * 16 + tid], v);
            TF[tid] = v;
        }
        __syncthreads();

        // ---- rebuild A0 (A2 aliased it last step): x | tf | state | zeros
        for (int idx = tid; idx < 32 * 48; idx += NT) {
            int r = idx & 31, c = idx >> 5;      // c = 0..47
            float v = (c < 32) ? XS[r * 33 + c] : TF[c - 32];
            __nv_bfloat16 hi = __float2bfloat16(v);
            __nv_bfloat16 lo = __float2bfloat16(v - __bfloat162float(hi));
            A0h[r * AS + c] = hi;
            A0l[r * AS + c] = lo;
        }
        for (int idx = tid; idx < 32 * 128; idx += NT) {
            int r = idx >> 7, c = idx & 127;
            float v = state[(r0 + r) * 128 + c];
            __nv_bfloat16 hi = __float2bfloat16(v);
            __nv_bfloat16 lo = __float2bfloat16(v - __bfloat162float(hi));
            A0h[r * AS + 48 + c] = hi;
            A0l[r * AS + 48 + c] = lo;
        }
        for (int idx = tid; idx < 32 * 16; idx += NT) {
            int r = idx >> 4, c = idx & 15;
            __nv_bfloat16 z = __float2bfloat16(0.f);
            A0h[r * AS + 176 + c] = z;
            A0l[r * AS + 176 + c] = z;
        }
        // gemm_layer entry sync covers the rebuild

        gemm_layer<6>(g_whi + W0_OFF, g_wlo + W0_OFF, b0, A0h, A0l,
                      A1h, A1l, SBh, SBl, tid);
        gemm_layer<8>(g_whi + W1_OFF, g_wlo + W1_OFF, b1, A1h, A1l,
                      A0h, A0l, SBh, SBl, tid);            // A2 := A0 space
        gemm_layer<8>(g_whi + W2_OFF, g_wlo + W2_OFF, b2, A0h, A0l,
                      A1h, A1l, SBh, SBl, tid);
        __syncthreads();

        // ---- final 256 -> 32 (exact fp32): row = tid>>4, 2 cols at (tid&15)*2
        const int row = tid >> 4;
        const int cp  = tid & 15;
        unsigned long long f0 = 0ull;
        const __nv_bfloat16* inh = A1h + row * AS;
        const __nv_bfloat16* inl = A1l + row * AS;
#pragma unroll 4
        for (int k2 = 0; k2 < 256; k2 += 2) {
            __nv_bfloat162 ph = *reinterpret_cast<const __nv_bfloat162*>(inh + k2);
            __nv_bfloat162 pl = *reinterpret_cast<const __nv_bfloat162*>(inl + k2);
            float a0 = __bfloat162float(ph.x) + __bfloat162float(pl.x);
            float a1 = __bfloat162float(ph.y) + __bfloat162float(pl.y);
#pragma unroll
            for (int kk = 0; kk < 2; ++kk) {
                float a = kk ? a1 : a0;
                const float* wp = SWF + ((k2 + kk) << 5) + (cp << 1);
                unsigned long long w01 = *reinterpret_cast<const unsigned long long*>(wp);
                unsigned long long aa;
                PACK_DUP(aa, a);
                FMA2(f0, aa, w01);
            }
        }
        float e0, e1;
        UNPACK2(e0, e1, f0);
        float eps[2] = { e0 + bf[cp * 2], e1 + bf[cp * 2 + 1] };

        float sr = CF[0], srm1 = CF[1], c1 = CF[2], c2 = CF[3], sig = CF[4];
        unsigned fk0 = CFu[5], fk1 = CFu[6];

        const int R = r0 + row;
#pragma unroll
        for (int cc = 0; cc < 2; ++cc) {
            int   j  = (cp << 1) + cc;
            float xv = XS[row * 33 + j];
            float x0 = fminf(1.f, fmaxf(-1.f, sr * xv - srm1 * eps[cc]));
            float mean = c1 * x0 + c2 * xv;
            if (i != 0) {
                unsigned f = (unsigned)(R * 32 + j);
                unsigned b0r = 0u, b1r = f;
                threefry2x32(fk0, fk1, b0r, b1r);
                unsigned bits = b0r ^ b1r;
                float fv = __uint_as_float((bits >> 9) | 0x3f800000u) - 1.0f;
                const float lo = -0.99999994f;
                float u   = fmaxf(lo, fmaf(fv, 2.0f, lo));
                float nrm = 1.4142135623730951f * erfinv_xla(u);
                XS[row * 33 + j] = mean + sig * nrm;
            } else {
                float xf = fminf(1.f, fmaxf(-1.f, mean));
                XS[row * 33 + j] = xf;
                outp[R * 32 + j] = xf;
            }
        }
        __syncthreads();
    }
}

extern "C" void kernel_launch(void* const* d_in, const int* in_sizes, int n_in,
                              void* d_out, int out_size) {
    const float* state = (const float*)d_in[0];
    const float* xinit = (const float*)d_in[1];
    const float* w_t1  = (const float*)d_in[2];
    const float* b_t1  = (const float*)d_in[3];
    const float* w_t2  = (const float*)d_in[4];
    const float* b_t2  = (const float*)d_in[5];
    const float* w0    = (const float*)d_in[6];
    const float* b0    = (const float*)d_in[7];
    const float* w1    = (const float*)d_in[8];
    const float* b1    = (const float*)d_in[9];
    const float* w2    = (const float*)d_in[10];
    const float* b2    = (const float*)d_in[11];
    const float* wf    = (const float*)d_in[12];
    const float* bf    = (const float*)d_in[13];
    float* outp = (float*)d_out;

    cudaFuncSetAttribute(diff_all, cudaFuncAttributeMaxDynamicSharedMemorySize, SMEM_BYTES);

    split_weights<<<(W_TOT + 255) / 256, 256>>>(w0, w1, w2);
    diff_all<<<NB, NT, SMEM_BYTES>>>(state, xinit,
        w_t1, b_t1, w_t2, b_t2,
        b0, b1, b2, wf, bf, outp);
}